// round 2
// baseline (speedup 1.0000x reference)
#include <cuda_runtime.h>

#define BB 4
#define SS 512
#define HH 256

// Scratch for projected rows (allocation-free requirement -> __device__ globals)
__device__ float g_ht [BB * SS * HH];   // h @ W_t + b_h
__device__ float g_htp[BB * SS * HH];   // h @ W_t_prime

__device__ __forceinline__ float tanh_fast(float x) {
    float y;
    asm("tanh.approx.f32 %0, %1;" : "=f"(y) : "f"(x));
    return y;
}

// ---------------------------------------------------------------------------
// Stage 1: ht = h @ W_t + b_h ;  htp = h @ W_t_prime
// Each block computes 8 output rows for all 256 k; W elements are reused
// across the 8 rows in registers (16 FFMA per 2 LDG).
// ---------------------------------------------------------------------------
__global__ void __launch_bounds__(256)
proj_kernel(const float* __restrict__ h,
            const float* __restrict__ Wt,
            const float* __restrict__ Wtp,
            const float* __restrict__ bh)
{
    constexpr int ROWS = 8;
    __shared__ float sh[ROWS][HH];
    const int row0 = blockIdx.x * ROWS;
    const int k = threadIdx.x;

    for (int i = threadIdx.x; i < ROWS * HH; i += blockDim.x)
        sh[i >> 8][i & 255] = h[row0 * HH + i];
    __syncthreads();

    float acct[ROWS], accp[ROWS];
#pragma unroll
    for (int r = 0; r < ROWS; ++r) { acct[r] = 0.f; accp[r] = 0.f; }

    for (int hh = 0; hh < HH; ++hh) {
        const float wt = Wt [hh * HH + k];
        const float wp = Wtp[hh * HH + k];
#pragma unroll
        for (int r = 0; r < ROWS; ++r) {
            const float hv = sh[r][hh];
            acct[r] = fmaf(hv, wt, acct[r]);
            accp[r] = fmaf(hv, wp, accp[r]);
        }
    }

    const float bias = bh[k];
#pragma unroll
    for (int r = 0; r < ROWS; ++r) {
        g_ht [(row0 + r) * HH + k] = acct[r] + bias;
        g_htp[(row0 + r) * HH + k] = accp[r];
    }
}

// ---------------------------------------------------------------------------
// Stage 2: one block per (b, t) row.
//   scores[tp] = W_a . tanh(ht[t] + htp[tp]) + b_a
//   w = softmax(sigmoid(scores));  out[t] = sum_tp w[tp] * h[b, tp, :]
// Warp-per-tp (8 warps stride over 512 tp), 32 lanes split H=256 (8 each).
// ---------------------------------------------------------------------------
__global__ void __launch_bounds__(256)
attn_kernel(const float* __restrict__ hin,
            const float* __restrict__ Wa,
            const float* __restrict__ ba,
            float* __restrict__ out,
            float* __restrict__ wts)
{
    const int bt   = blockIdx.x;            // 0 .. B*S-1
    const int b    = bt >> 9;               // / S
    const int tid  = threadIdx.x;
    const int warp = tid >> 5;
    const int lane = tid & 31;

    __shared__ float p[SS];
    __shared__ float red[8];

    const float* htr = g_ht  + bt * HH;
    const float* hpb = g_htp + (size_t)b * SS * HH;

    const float4* htv = (const float4*)(htr + lane * 8);
    const float4  t0  = htv[0], t1 = htv[1];
    const float4* wav = (const float4*)(Wa + lane * 8);
    const float4  a0  = wav[0], a1 = wav[1];
    const float   ba_v = ba[0];

    for (int tp = warp; tp < SS; tp += 8) {
        const float4* hp = (const float4*)(hpb + tp * HH + lane * 8);
        const float4 x0 = hp[0];
        const float4 x1 = hp[1];
        float acc;
        acc =      a0.x * tanh_fast(t0.x + x0.x);
        acc = fmaf(a0.y, tanh_fast(t0.y + x0.y), acc);
        acc = fmaf(a0.z, tanh_fast(t0.z + x0.z), acc);
        acc = fmaf(a0.w, tanh_fast(t0.w + x0.w), acc);
        acc = fmaf(a1.x, tanh_fast(t1.x + x1.x), acc);
        acc = fmaf(a1.y, tanh_fast(t1.y + x1.y), acc);
        acc = fmaf(a1.z, tanh_fast(t1.z + x1.z), acc);
        acc = fmaf(a1.w, tanh_fast(t1.w + x1.w), acc);
#pragma unroll
        for (int off = 16; off > 0; off >>= 1)
            acc += __shfl_xor_sync(0xffffffffu, acc, off);
        if (lane == 0) {
            const float s  = acc + ba_v;
            const float sg = __fdividef(1.f, 1.f + __expf(-s));  // sigmoid
            p[tp] = __expf(sg);                                  // exp for softmax
        }
    }
    __syncthreads();

    // Block-wide sum of p[0..511]
    float v = p[tid] + p[tid + 256];
#pragma unroll
    for (int off = 16; off > 0; off >>= 1)
        v += __shfl_xor_sync(0xffffffffu, v, off);
    if (lane == 0) red[warp] = v;
    __syncthreads();
    const float tot = red[0] + red[1] + red[2] + red[3]
                    + red[4] + red[5] + red[6] + red[7];
    const float inv = 1.0f / tot;

    const float w0 = p[tid]       * inv;
    const float w1 = p[tid + 256] * inv;
    if (wts) {
        wts[(size_t)bt * SS + tid]       = w0;
        wts[(size_t)bt * SS + tid + 256] = w1;
    }
    p[tid]       = w0;   // safe: each thread rewrites only its own entries
    p[tid + 256] = w1;
    __syncthreads();

    // out[bt, tid] = sum_tp w[tp] * h[b, tp, tid]
    const float* hb = hin + (size_t)b * SS * HH + tid;
    float acc = 0.f;
#pragma unroll 4
    for (int tp = 0; tp < SS; ++tp)
        acc = fmaf(p[tp], hb[(size_t)tp * HH], acc);
    out[(size_t)bt * HH + tid] = acc;
}

// ---------------------------------------------------------------------------
extern "C" void kernel_launch(void* const* d_in, const int* in_sizes, int n_in,
                              void* d_out, int out_size)
{
    const float* h   = (const float*)d_in[0];
    const float* Wt  = (const float*)d_in[1];
    const float* Wtp = (const float*)d_in[2];
    const float* bh  = (const float*)d_in[3];
    const float* Wa  = (const float*)d_in[4];
    const float* ba  = (const float*)d_in[5];

    float* out = (float*)d_out;
    float* wts = nullptr;
    const int nOut = BB * SS * HH;   // 524288
    const int nW   = BB * SS * SS;   // 1048576
    if (out_size >= nOut + nW) wts = out + nOut;

    proj_kernel<<<BB * SS / 8, 256>>>(h, Wt, Wtp, bh);
    attn_kernel<<<BB * SS, 256>>>(h, Wa, ba, out, wts);
}

// round 3
// speedup vs baseline: 1.0028x; 1.0028x over previous
#include <cuda_runtime.h>
#include <cuda_fp16.h>

#define BB 4
#define SS 512
#define HH 256
#define H4 (HH / 4)        // 64 groups of 4 h-elements
#define TT 8               // t-rows per attention block
#define TPT 32             // tp per smem tile (one per lane)
#define NTILE (SS / TPT)   // 16

// Scratch (allocation-free rule -> __device__ globals)
__device__ __half g_ht_h[BB * SS * HH];      // [bt][h]   ht + b_h, half
__device__ uint2  g_htpT[BB * H4 * SS];      // [b][h4][tp] 4 packed halves of htp

__device__ __forceinline__ float tanh_fast(float x) {
    float y; asm("tanh.approx.f32 %0, %1;" : "=f"(y) : "f"(x)); return y;
}
__device__ __forceinline__ unsigned tanh2u(unsigned x) {
    unsigned y; asm("tanh.approx.f16x2 %0, %1;" : "=r"(y) : "r"(x)); return y;
}
__device__ __forceinline__ __half2 u2h(unsigned x) { return *reinterpret_cast<__half2*>(&x); }
__device__ __forceinline__ unsigned h2u(__half2 x) { return *reinterpret_cast<unsigned*>(&x); }

// ---------------------------------------------------------------------------
// Stage 1: projections. Block computes 8 rows x 256 k in fp32 registers,
// then stores ht as half (row-major) and htp as half packed-transposed.
// ---------------------------------------------------------------------------
__global__ void __launch_bounds__(256)
proj_kernel(const float* __restrict__ h,
            const float* __restrict__ Wt,
            const float* __restrict__ Wtp,
            const float* __restrict__ bh)
{
    constexpr int ROWS = 8;
    __shared__ float sh[ROWS][HH];
    const int row0 = blockIdx.x * ROWS;
    const int k = threadIdx.x;

    for (int i = threadIdx.x; i < ROWS * HH; i += blockDim.x)
        sh[i >> 8][i & 255] = h[row0 * HH + i];
    __syncthreads();

    float acct[ROWS], accp[ROWS];
#pragma unroll
    for (int r = 0; r < ROWS; ++r) { acct[r] = 0.f; accp[r] = 0.f; }

    for (int hh = 0; hh < HH; ++hh) {
        const float wt = Wt [hh * HH + k];
        const float wp = Wtp[hh * HH + k];
#pragma unroll
        for (int r = 0; r < ROWS; ++r) {
            const float hv = sh[r][hh];
            acct[r] = fmaf(hv, wt, acct[r]);
            accp[r] = fmaf(hv, wp, accp[r]);
        }
    }

    const float bias = bh[k];
    __half* htpT = reinterpret_cast<__half*>(g_htpT);
#pragma unroll
    for (int r = 0; r < ROWS; ++r) {
        const int row = row0 + r;          // = bt
        const int b   = row >> 9;
        const int tp  = row & (SS - 1);
        g_ht_h[row * HH + k] = __float2half(acct[r] + bias);
        // htpT element [b][k/4][tp], half slot k%4
        htpT[(((size_t)b * H4 + (k >> 2)) * SS + tp) * 4 + (k & 3)] = __float2half(accp[r]);
    }
}

// ---------------------------------------------------------------------------
// Stage 2 (fused): scores + sigmoid + softmax + output GEMM.
// Block = 8 t-rows of one batch. Warp w owns t-row w; lanes own tp columns.
// htp tiles live in smem (half2-packed, transposed); ht||Wa uniform LDS.128.
// ---------------------------------------------------------------------------
__global__ void __launch_bounds__(256)
attn_kernel(const float* __restrict__ hin,
            const float* __restrict__ Wa,
            const float* __restrict__ ba,
            float* __restrict__ out,
            float* __restrict__ wts)
{
    const int bt0 = blockIdx.x * TT;
    const int b   = bt0 >> 9;
    const int tid = threadIdx.x;
    const int w   = tid >> 5;     // warp == local t-row
    const int lane= tid & 31;

    __shared__ uint4 su[TT][H4];            // {ht01, ht23, wa01, wa23} per (t,h4)  8KB
    __shared__ float wsm[TT][SS];           // unnormalized p, then weights        16KB
    union SmemU { uint2 tile[H4][TPT];      // htp tile                            16KB
                  float wT[SS][8]; };       // transposed weights (epilogue)
    __shared__ SmemU uu;

    // Build su: ht halves from g_ht_h, Wa converted to half pairs.
    for (int e = tid; e < TT * H4; e += 256) {
        const int t  = e / H4;
        const int h4 = e % H4;
        const uint2 ht4 = reinterpret_cast<const uint2*>(g_ht_h)[(bt0 + t) * (HH / 4) + h4];
        const float4 wa4 = reinterpret_cast<const float4*>(Wa)[h4];
        const __half2 wa01 = __floats2half2_rn(wa4.x, wa4.y);
        const __half2 wa23 = __floats2half2_rn(wa4.z, wa4.w);
        su[t][h4] = make_uint4(ht4.x, ht4.y, h2u(wa01), h2u(wa23));
    }
    const float bav = ba[0];

    float ssum = 0.f;
    float pv[NTILE];

    for (int tile = 0; tile < NTILE; ++tile) {
        // Load htp tile [H4][TPT]; consecutive tid -> consecutive tp (coalesced).
        __syncthreads();
        for (int i = tid; i < H4 * TPT; i += 256) {
            const int h4 = i / TPT;
            const int tp = i % TPT;
            uu.tile[h4][tp] = g_htpT[((size_t)b * H4 + h4) * SS + tile * TPT + tp];
        }
        __syncthreads();

        // Each lane: full H dot for (t=w, tp=tile*32+lane).
        float fa = 0.f;
        __half2 acc = __floats2half2_rn(0.f, 0.f);
#pragma unroll 1
        for (int hb = 0; hb < H4 / 4; ++hb) {       // fold every 4 h4 (8 HFMA2)
#pragma unroll
            for (int j = 0; j < 4; ++j) {
                const int h4 = hb * 4 + j;
                const uint4 u = su[w][h4];
                const uint2 x = uu.tile[h4][lane];
                const __half2 a0 = __hadd2(u2h(u.x), u2h(x.x));
                const __half2 a1 = __hadd2(u2h(u.y), u2h(x.y));
                const __half2 t0 = u2h(tanh2u(h2u(a0)));
                const __half2 t1 = u2h(tanh2u(h2u(a1)));
                acc = __hfma2(u2h(u.z), t0, acc);
                acc = __hfma2(u2h(u.w), t1, acc);
            }
            const float2 f = __half22float2(acc);
            fa += f.x + f.y;
            acc = __floats2half2_rn(0.f, 0.f);
        }
        const float s  = fa + bav;
        const float sg = 0.5f * tanh_fast(0.5f * s) + 0.5f;  // sigmoid
        const float p  = __expf(sg);
        ssum += p;
        pv[tile] = p;
        wsm[w][tile * TPT + lane] = p;
    }

    // Row sum over lanes (each lane holds distinct tp's)
#pragma unroll
    for (int off = 16; off > 0; off >>= 1)
        ssum += __shfl_xor_sync(0xffffffffu, ssum, off);
    const float inv = 1.0f / ssum;

    __syncthreads();   // tile region done -> reuse as wT
#pragma unroll
    for (int tile = 0; tile < NTILE; ++tile) {
        const int tp = tile * TPT + lane;
        const float wv = pv[tile] * inv;
        uu.wT[tp][w] = wv;
        if (wts) wts[(size_t)(bt0 + w) * SS + tp] = wv;
    }
    __syncthreads();

    // Output GEMM: thread tid owns k; each h load reused across 8 t-rows.
    const int k = tid;
    float facc[TT];
#pragma unroll
    for (int r = 0; r < TT; ++r) facc[r] = 0.f;
    const float* hb = hin + (size_t)b * SS * HH + k;
#pragma unroll 4
    for (int tp = 0; tp < SS; ++tp) {
        const float hv = hb[(size_t)tp * HH];
        const float4 wA = *reinterpret_cast<const float4*>(&uu.wT[tp][0]);
        const float4 wB = *reinterpret_cast<const float4*>(&uu.wT[tp][4]);
        facc[0] = fmaf(wA.x, hv, facc[0]);
        facc[1] = fmaf(wA.y, hv, facc[1]);
        facc[2] = fmaf(wA.z, hv, facc[2]);
        facc[3] = fmaf(wA.w, hv, facc[3]);
        facc[4] = fmaf(wB.x, hv, facc[4]);
        facc[5] = fmaf(wB.y, hv, facc[5]);
        facc[6] = fmaf(wB.z, hv, facc[6]);
        facc[7] = fmaf(wB.w, hv, facc[7]);
    }
#pragma unroll
    for (int r = 0; r < TT; ++r)
        out[(size_t)(bt0 + r) * HH + k] = facc[r];
}

// ---------------------------------------------------------------------------
extern "C" void kernel_launch(void* const* d_in, const int* in_sizes, int n_in,
                              void* d_out, int out_size)
{
    const float* h   = (const float*)d_in[0];
    const float* Wt  = (const float*)d_in[1];
    const float* Wtp = (const float*)d_in[2];
    const float* bh  = (const float*)d_in[3];
    const float* Wa  = (const float*)d_in[4];
    const float* ba  = (const float*)d_in[5];

    float* out = (float*)d_out;
    float* wts = nullptr;
    const int nOut = BB * SS * HH;   // 524288
    const int nW   = BB * SS * SS;   // 1048576
    if (out_size >= nOut + nW) wts = out + nOut;

    proj_kernel<<<BB * SS / 8, 256>>>(h, Wt, Wtp, bh);
    attn_kernel<<<BB * SS / TT, 256>>>(h, Wa, ba, out, wts);
}

// round 4
// speedup vs baseline: 1.6965x; 1.6919x over previous
#include <cuda_runtime.h>
#include <cuda_fp16.h>

#define BB 4
#define SS 512
#define HH 256
#define H4 (HH / 4)        // 64 groups of 4 h-elements

// Scratch (allocation-free rule -> __device__ globals)
__device__ __half g_ht_h[BB * SS * HH];      // [bt][h]   ht + b_h, half
__device__ uint2  g_htpT[BB * H4 * SS];      // [b][h4][tp] 4 packed halves of htp
__device__ float  g_p[BB * SS * SS];         // unnormalized exp(sigmoid(score))

__device__ __forceinline__ float tanh_fast(float x) {
    float y; asm("tanh.approx.f32 %0, %1;" : "=f"(y) : "f"(x)); return y;
}
__device__ __forceinline__ unsigned tanh2u(unsigned x) {
    unsigned y; asm("tanh.approx.f16x2 %0, %1;" : "=r"(y) : "r"(x)); return y;
}
__device__ __forceinline__ __half2 u2h(unsigned x) { return *reinterpret_cast<__half2*>(&x); }
__device__ __forceinline__ unsigned h2u(__half2 x) { return *reinterpret_cast<unsigned*>(&x); }

// ---------------------------------------------------------------------------
// Stage 1: projections. Block computes 8 rows x 256 k in fp32 registers,
// then stores ht as half (row-major) and htp as half packed-transposed.
// ---------------------------------------------------------------------------
__global__ void __launch_bounds__(256)
proj_kernel(const float* __restrict__ h,
            const float* __restrict__ Wt,
            const float* __restrict__ Wtp,
            const float* __restrict__ bh)
{
    constexpr int ROWS = 8;
    __shared__ float sh[ROWS][HH];
    const int row0 = blockIdx.x * ROWS;
    const int k = threadIdx.x;

    for (int i = threadIdx.x; i < ROWS * HH; i += blockDim.x)
        sh[i >> 8][i & 255] = h[row0 * HH + i];
    __syncthreads();

    float acct[ROWS], accp[ROWS];
#pragma unroll
    for (int r = 0; r < ROWS; ++r) { acct[r] = 0.f; accp[r] = 0.f; }

    for (int hh = 0; hh < HH; ++hh) {
        const float wt = Wt [hh * HH + k];
        const float wp = Wtp[hh * HH + k];
#pragma unroll
        for (int r = 0; r < ROWS; ++r) {
            const float hv = sh[r][hh];
            acct[r] = fmaf(hv, wt, acct[r]);
            accp[r] = fmaf(hv, wp, accp[r]);
        }
    }

    const float bias = bh[k];
    __half* htpT = reinterpret_cast<__half*>(g_htpT);
#pragma unroll
    for (int r = 0; r < ROWS; ++r) {
        const int row = row0 + r;          // = bt
        const int b   = row >> 9;
        const int tp  = row & (SS - 1);
        g_ht_h[row * HH + k] = __float2half(acct[r] + bias);
        htpT[(((size_t)b * H4 + (k >> 2)) * SS + tp) * 4 + (k & 3)] = __float2half(accp[r]);
    }
}

// ---------------------------------------------------------------------------
// Stage 2: pure (t, tp) score map, no normalization.
//   p[bt][tp] = exp(sigmoid(Wa . tanh(ht[t] + htp[tp]) + ba))
// grid = (16 tp-tiles, 128 row-groups). Block: 16 t-rows x 32 tp.
// Warp w owns rows {2w, 2w+1}; lane owns tp = tile*32 + lane.
// su (ht||Wa halves) in smem; htp via coalesced LDG (L1-resident tile).
// ---------------------------------------------------------------------------
__global__ void __launch_bounds__(256)
score_kernel(const float* __restrict__ Wa,
             const float* __restrict__ ba)
{
    const int bt0 = blockIdx.y * 16;        // 16 rows, same batch (16 | 512)
    const int b   = bt0 >> 9;
    const int tid = threadIdx.x;
    const int w   = tid >> 5;
    const int lane= tid & 31;

    __shared__ uint4 su[16][H4];            // {ht01, ht23, wa01, wa23}  16KB

    for (int e = tid; e < 16 * H4; e += 256) {
        const int t  = e >> 6;
        const int h4 = e & 63;
        const uint2 ht4 = reinterpret_cast<const uint2*>(g_ht_h)[(bt0 + t) * (HH / 4) + h4];
        const float4 wa4 = reinterpret_cast<const float4*>(Wa)[h4];
        su[t][h4] = make_uint4(ht4.x, ht4.y,
                               h2u(__floats2half2_rn(wa4.x, wa4.y)),
                               h2u(__floats2half2_rn(wa4.z, wa4.w)));
    }
    __syncthreads();

    const float bav = ba[0];
    const int   tp  = blockIdx.x * 32 + lane;
    const int   r0  = 2 * w, r1 = 2 * w + 1;
    const uint2* hp = g_htpT + (size_t)b * H4 * SS + tp;

    float fa0 = 0.f, fa1 = 0.f;
    __half2 z = __floats2half2_rn(0.f, 0.f);
    __half2 acc0 = z, acc1 = z;

#pragma unroll 1
    for (int hb = 0; hb < 16; ++hb) {       // fold to fp32 every 4 h4
#pragma unroll
        for (int j = 0; j < 4; ++j) {
            const int h4 = hb * 4 + j;
            const uint2 x  = hp[(size_t)h4 * SS];
            const __half2 xa = u2h(x.x), xb = u2h(x.y);
            const uint4 u0 = su[r0][h4];
            const uint4 u1 = su[r1][h4];
            acc0 = __hfma2(u2h(u0.z), u2h(tanh2u(h2u(__hadd2(u2h(u0.x), xa)))), acc0);
            acc0 = __hfma2(u2h(u0.w), u2h(tanh2u(h2u(__hadd2(u2h(u0.y), xb)))), acc0);
            acc1 = __hfma2(u2h(u1.z), u2h(tanh2u(h2u(__hadd2(u2h(u1.x), xa)))), acc1);
            acc1 = __hfma2(u2h(u1.w), u2h(tanh2u(h2u(__hadd2(u2h(u1.y), xb)))), acc1);
        }
        const float2 f0 = __half22float2(acc0);
        const float2 f1 = __half22float2(acc1);
        fa0 += f0.x + f0.y;
        fa1 += f1.x + f1.y;
        acc0 = z; acc1 = z;
    }

    const float s0 = fa0 + bav;
    const float s1 = fa1 + bav;
    const float p0 = __expf(0.5f * tanh_fast(0.5f * s0) + 0.5f);
    const float p1 = __expf(0.5f * tanh_fast(0.5f * s1) + 0.5f);
    g_p[(size_t)(bt0 + r0) * SS + tp] = p0;
    g_p[(size_t)(bt0 + r1) * SS + tp] = p1;
}

// ---------------------------------------------------------------------------
// Stage 3: rowsum + normalize + output GEMM.
// Block = 8 t-rows of one batch; thread owns k. h loads reused across 8 rows.
// out[t] = (1/rowsum) * sum_tp p[t,tp] h[b,tp,:]; wts = p/rowsum.
// ---------------------------------------------------------------------------
__global__ void __launch_bounds__(256)
out_kernel(const float* __restrict__ hin,
           float* __restrict__ out,
           float* __restrict__ wts)
{
    const int bt0 = blockIdx.x * 8;
    const int b   = bt0 >> 9;
    const int tid = threadIdx.x;
    const int w   = tid >> 5;
    const int lane= tid & 31;

    __shared__ float pT[SS][8];             // transposed p (unnormalized)  16KB
    __shared__ float rinv[8];

    // Load p coalesced, store transposed.
    for (int e = tid; e < 8 * SS; e += 256) {
        const int t  = e >> 9;
        const int tp = e & (SS - 1);
        pT[tp][t] = g_p[(size_t)(bt0 + t) * SS + tp];
    }
    __syncthreads();

    // Rowsum: warp w owns row w; lanes stride tp.
    {
        float s = 0.f;
        for (int tp = lane; tp < SS; tp += 32) s += pT[tp][w];
#pragma unroll
        for (int off = 16; off > 0; off >>= 1)
            s += __shfl_xor_sync(0xffffffffu, s, off);
        if (lane == 0) rinv[w] = 1.0f / s;
    }
    __syncthreads();

    // Normalized weights output.
    if (wts) {
        for (int e = tid; e < 8 * SS; e += 256) {
            const int t  = e >> 9;
            const int tp = e & (SS - 1);
            wts[(size_t)(bt0 + t) * SS + tp] = pT[tp][t] * rinv[t];
        }
    }

    // GEMM with unnormalized p, scale at the end.
    const int k = tid;
    float facc[8];
#pragma unroll
    for (int r = 0; r < 8; ++r) facc[r] = 0.f;
    const float* hb = hin + (size_t)b * SS * HH + k;
#pragma unroll 4
    for (int tp = 0; tp < SS; ++tp) {
        const float hv = hb[(size_t)tp * HH];
        const float4 wA = *reinterpret_cast<const float4*>(&pT[tp][0]);
        const float4 wB = *reinterpret_cast<const float4*>(&pT[tp][4]);
        facc[0] = fmaf(wA.x, hv, facc[0]);
        facc[1] = fmaf(wA.y, hv, facc[1]);
        facc[2] = fmaf(wA.z, hv, facc[2]);
        facc[3] = fmaf(wA.w, hv, facc[3]);
        facc[4] = fmaf(wB.x, hv, facc[4]);
        facc[5] = fmaf(wB.y, hv, facc[5]);
        facc[6] = fmaf(wB.z, hv, facc[6]);
        facc[7] = fmaf(wB.w, hv, facc[7]);
    }
#pragma unroll
    for (int r = 0; r < 8; ++r)
        out[(size_t)(bt0 + r) * HH + k] = facc[r] * rinv[r];
}

// ---------------------------------------------------------------------------
extern "C" void kernel_launch(void* const* d_in, const int* in_sizes, int n_in,
                              void* d_out, int out_size)
{
    const float* h   = (const float*)d_in[0];
    const float* Wt  = (const float*)d_in[1];
    const float* Wtp = (const float*)d_in[2];
    const float* bh  = (const float*)d_in[3];
    const float* Wa  = (const float*)d_in[4];
    const float* ba  = (const float*)d_in[5];

    float* out = (float*)d_out;
    float* wts = nullptr;
    const int nOut = BB * SS * HH;   // 524288
    const int nW   = BB * SS * SS;   // 1048576
    if (out_size >= nOut + nW) wts = out + nOut;

    proj_kernel<<<BB * SS / 8, 256>>>(h, Wt, Wtp, bh);
    score_kernel<<<dim3(SS / 32, BB * SS / 16), 256>>>(Wa, ba);
    out_kernel<<<BB * SS / 8, 256>>>(h, out, wts);
}

// round 5
// speedup vs baseline: 1.7853x; 1.0523x over previous
#include <cuda_runtime.h>
#include <cuda_fp16.h>

#define BB 4
#define SS 512
#define HH 256
#define H4 (HH / 4)        // 64 groups of 4 h-elements

// Scratch (allocation-free rule -> __device__ globals)
__device__ __half g_ht_h[BB * SS * HH];      // [bt][h]   ht + b_h, half
__device__ uint2  g_htpT[BB * H4 * SS];      // [b][h4][tp] 4 packed halves of htp
__device__ float  g_p[BB * SS * SS];         // unnormalized exp(sigmoid(score))

__device__ __forceinline__ float tanh_fast(float x) {
    float y; asm("tanh.approx.f32 %0, %1;" : "=f"(y) : "f"(x)); return y;
}
__device__ __forceinline__ unsigned tanh2u(unsigned x) {
    unsigned y; asm("tanh.approx.f16x2 %0, %1;" : "=r"(y) : "r"(x)); return y;
}
__device__ __forceinline__ __half2 u2h(unsigned x) { return *reinterpret_cast<__half2*>(&x); }
__device__ __forceinline__ unsigned h2u(__half2 x) { return *reinterpret_cast<unsigned*>(&x); }

// ---------------------------------------------------------------------------
// Stage 1: projections, 512 threads. Half 0 of the block computes the Wt
// stream, half 1 the Wtp stream (halves per-thread latency chain, doubles
// resident warps vs R4). 8 rows register-tiled; W reused across rows.
// ---------------------------------------------------------------------------
__global__ void __launch_bounds__(512)
proj_kernel(const float* __restrict__ h,
            const float* __restrict__ Wt,
            const float* __restrict__ Wtp,
            const float* __restrict__ bh)
{
    constexpr int ROWS = 8;
    __shared__ float sh[ROWS][HH];
    const int row0 = blockIdx.x * ROWS;
    const int tid  = threadIdx.x;
    const int half = tid >> 8;          // 0: Wt, 1: Wtp
    const int k    = tid & 255;

    for (int i = tid; i < ROWS * HH; i += 512)
        sh[i >> 8][i & 255] = h[row0 * HH + i];
    __syncthreads();

    const float* __restrict__ W = half ? Wtp : Wt;
    float acc[ROWS];
#pragma unroll
    for (int r = 0; r < ROWS; ++r) acc[r] = 0.f;

#pragma unroll 4
    for (int hh = 0; hh < HH; ++hh) {
        const float wv = W[hh * HH + k];
#pragma unroll
        for (int r = 0; r < ROWS; ++r)
            acc[r] = fmaf(sh[r][hh], wv, acc[r]);
    }

    if (half == 0) {
        const float bias = bh[k];
#pragma unroll
        for (int r = 0; r < ROWS; ++r)
            g_ht_h[(row0 + r) * HH + k] = __float2half(acc[r] + bias);
    } else {
        __half* htpT = reinterpret_cast<__half*>(g_htpT);
#pragma unroll
        for (int r = 0; r < ROWS; ++r) {
            const int row = row0 + r;
            const int b   = row >> 9;
            const int tp  = row & (SS - 1);
            htpT[(((size_t)b * H4 + (k >> 2)) * SS + tp) * 4 + (k & 3)] = __float2half(acc[r]);
        }
    }
}

// ---------------------------------------------------------------------------
// Stage 2: pure (t, tp) score map, no normalization. (unchanged from R4)
//   p[bt][tp] = exp(sigmoid(Wa . tanh(ht[t] + htp[tp]) + ba))
// ---------------------------------------------------------------------------
__global__ void __launch_bounds__(256)
score_kernel(const float* __restrict__ Wa,
             const float* __restrict__ ba)
{
    const int bt0 = blockIdx.y * 16;        // 16 rows, same batch (16 | 512)
    const int b   = bt0 >> 9;
    const int tid = threadIdx.x;
    const int w   = tid >> 5;
    const int lane= tid & 31;

    __shared__ uint4 su[16][H4];            // {ht01, ht23, wa01, wa23}  16KB

    for (int e = tid; e < 16 * H4; e += 256) {
        const int t  = e >> 6;
        const int h4 = e & 63;
        const uint2 ht4 = reinterpret_cast<const uint2*>(g_ht_h)[(bt0 + t) * (HH / 4) + h4];
        const float4 wa4 = reinterpret_cast<const float4*>(Wa)[h4];
        su[t][h4] = make_uint4(ht4.x, ht4.y,
                               h2u(__floats2half2_rn(wa4.x, wa4.y)),
                               h2u(__floats2half2_rn(wa4.z, wa4.w)));
    }
    __syncthreads();

    const float bav = ba[0];
    const int   tp  = blockIdx.x * 32 + lane;
    const int   r0  = 2 * w, r1 = 2 * w + 1;
    const uint2* hp = g_htpT + (size_t)b * H4 * SS + tp;

    float fa0 = 0.f, fa1 = 0.f;
    __half2 z = __floats2half2_rn(0.f, 0.f);
    __half2 acc0 = z, acc1 = z;

#pragma unroll 1
    for (int hb = 0; hb < 16; ++hb) {       // fold to fp32 every 4 h4
#pragma unroll
        for (int j = 0; j < 4; ++j) {
            const int h4 = hb * 4 + j;
            const uint2 x  = hp[(size_t)h4 * SS];
            const __half2 xa = u2h(x.x), xb = u2h(x.y);
            const uint4 u0 = su[r0][h4];
            const uint4 u1 = su[r1][h4];
            acc0 = __hfma2(u2h(u0.z), u2h(tanh2u(h2u(__hadd2(u2h(u0.x), xa)))), acc0);
            acc0 = __hfma2(u2h(u0.w), u2h(tanh2u(h2u(__hadd2(u2h(u0.y), xb)))), acc0);
            acc1 = __hfma2(u2h(u1.z), u2h(tanh2u(h2u(__hadd2(u2h(u1.x), xa)))), acc1);
            acc1 = __hfma2(u2h(u1.w), u2h(tanh2u(h2u(__hadd2(u2h(u1.y), xb)))), acc1);
        }
        const float2 f0 = __half22float2(acc0);
        const float2 f1 = __half22float2(acc1);
        fa0 += f0.x + f0.y;
        fa1 += f1.x + f1.y;
        acc0 = z; acc1 = z;
    }

    const float s0 = fa0 + bav;
    const float s1 = fa1 + bav;
    const float p0 = __expf(0.5f * tanh_fast(0.5f * s0) + 0.5f);
    const float p1 = __expf(0.5f * tanh_fast(0.5f * s1) + 0.5f);
    g_p[(size_t)(bt0 + r0) * SS + tp] = p0;
    g_p[(size_t)(bt0 + r1) * SS + tp] = p1;
}

// ---------------------------------------------------------------------------
// Stage 3: rowsum + normalize + output GEMM, 512 threads.
// Thread (seg, k): seg 0 sums tp in [0,256), seg 1 in [256,512); partials
// combined through smem. Each block reads h[b] once (reused over 8 rows).
// ---------------------------------------------------------------------------
__global__ void __launch_bounds__(512)
out_kernel(const float* __restrict__ hin,
           float* __restrict__ out,
           float* __restrict__ wts)
{
    const int bt0 = blockIdx.x * 8;
    const int b   = bt0 >> 9;
    const int tid = threadIdx.x;
    const int w   = tid >> 5;
    const int lane= tid & 31;
    const int seg = tid >> 8;           // 0 or 1 (tp half)
    const int k   = tid & 255;

    __shared__ float pT[SS][8];             // transposed p (unnormalized)  16KB
    __shared__ float part[8][HH];           // seg-1 partial sums           8KB
    __shared__ float rinv[8];

    // Load p coalesced, store transposed.
    for (int e = tid; e < 8 * SS; e += 512) {
        const int t  = e >> 9;
        const int tp = e & (SS - 1);
        pT[tp][t] = g_p[(size_t)(bt0 + t) * SS + tp];
    }
    __syncthreads();

    // Rowsum: warps 0..7 own rows 0..7 (warps 8..15 idle here).
    if (w < 8) {
        float s = 0.f;
        for (int tp = lane; tp < SS; tp += 32) s += pT[tp][w];
#pragma unroll
        for (int off = 16; off > 0; off >>= 1)
            s += __shfl_xor_sync(0xffffffffu, s, off);
        if (lane == 0) rinv[w] = 1.0f / s;
    }
    __syncthreads();

    // Normalized weights output.
    if (wts) {
        for (int e = tid; e < 8 * SS; e += 512) {
            const int t  = e >> 9;
            const int tp = e & (SS - 1);
            wts[(size_t)(bt0 + t) * SS + tp] = pT[tp][t] * rinv[t];
        }
    }

    // GEMM with unnormalized p over this segment's tp range.
    float facc[8];
#pragma unroll
    for (int r = 0; r < 8; ++r) facc[r] = 0.f;
    const float* hb = hin + (size_t)b * SS * HH + k;
    const int tp0 = seg * 256;
#pragma unroll 4
    for (int i = 0; i < 256; ++i) {
        const int tp = tp0 + i;
        const float hv = hb[(size_t)tp * HH];
        const float4 wA = *reinterpret_cast<const float4*>(&pT[tp][0]);
        const float4 wB = *reinterpret_cast<const float4*>(&pT[tp][4]);
        facc[0] = fmaf(wA.x, hv, facc[0]);
        facc[1] = fmaf(wA.y, hv, facc[1]);
        facc[2] = fmaf(wA.z, hv, facc[2]);
        facc[3] = fmaf(wA.w, hv, facc[3]);
        facc[4] = fmaf(wB.x, hv, facc[4]);
        facc[5] = fmaf(wB.y, hv, facc[5]);
        facc[6] = fmaf(wB.z, hv, facc[6]);
        facc[7] = fmaf(wB.w, hv, facc[7]);
    }

    if (seg == 1) {
#pragma unroll
        for (int r = 0; r < 8; ++r) part[r][k] = facc[r];
    }
    __syncthreads();
    if (seg == 0) {
#pragma unroll
        for (int r = 0; r < 8; ++r)
            out[(size_t)(bt0 + r) * HH + k] = (facc[r] + part[r][k]) * rinv[r];
    }
}

// ---------------------------------------------------------------------------
extern "C" void kernel_launch(void* const* d_in, const int* in_sizes, int n_in,
                              void* d_out, int out_size)
{
    const float* h   = (const float*)d_in[0];
    const float* Wt  = (const float*)d_in[1];
    const float* Wtp = (const float*)d_in[2];
    const float* bh  = (const float*)d_in[3];
    const float* Wa  = (const float*)d_in[4];
    const float* ba  = (const float*)d_in[5];

    float* out = (float*)d_out;
    float* wts = nullptr;
    const int nOut = BB * SS * HH;   // 524288
    const int nW   = BB * SS * SS;   // 1048576
    if (out_size >= nOut + nW) wts = out + nOut;

    proj_kernel<<<BB * SS / 8, 512>>>(h, Wt, Wtp, bh);
    score_kernel<<<dim3(SS / 32, BB * SS / 16), 256>>>(Wa, ba);
    out_kernel<<<BB * SS / 8, 512>>>(h, out, wts);
}

// round 6
// speedup vs baseline: 1.7956x; 1.0058x over previous
#include <cuda_runtime.h>
#include <cuda_fp16.h>

#define BB 4
#define SS 512
#define HH 256
#define H4 (HH / 4)        // 64 groups of 4 h-elements

// Scratch (allocation-free rule -> __device__ globals)
__device__ __half g_ht_h[BB * SS * HH];      // [bt][h]   ht + b_h, half
__device__ uint2  g_htpT[BB * H4 * SS];      // [b][h4][tp] 4 packed halves of htp
__device__ float  g_p[BB * SS * SS];         // unnormalized exp(sigmoid(score))

__device__ __forceinline__ float tanh_fast(float x) {
    float y; asm("tanh.approx.f32 %0, %1;" : "=f"(y) : "f"(x)); return y;
}
__device__ __forceinline__ unsigned tanh2u(unsigned x) {
    unsigned y; asm("tanh.approx.f16x2 %0, %1;" : "=r"(y) : "r"(x)); return y;
}
__device__ __forceinline__ __half2 u2h(unsigned x) { return *reinterpret_cast<__half2*>(&x); }
__device__ __forceinline__ unsigned h2u(__half2 x) { return *reinterpret_cast<unsigned*>(&x); }

// ---------------------------------------------------------------------------
// Stage 1: projections, 512 threads (half 0: Wt, half 1: Wtp).
// v3: hh unrolled by 4; h rows read as LDS.128 (4x fewer smem instrs),
// W loads batched 4-wide for MLP.
// ---------------------------------------------------------------------------
__global__ void __launch_bounds__(512)
proj_kernel(const float* __restrict__ h,
            const float* __restrict__ Wt,
            const float* __restrict__ Wtp,
            const float* __restrict__ bh)
{
    constexpr int ROWS = 8;
    __shared__ float sh[ROWS][HH];
    const int row0 = blockIdx.x * ROWS;
    const int tid  = threadIdx.x;
    const int half = tid >> 8;          // 0: Wt, 1: Wtp
    const int k    = tid & 255;

    for (int i = tid; i < ROWS * HH; i += 512)
        sh[i >> 8][i & 255] = h[row0 * HH + i];
    __syncthreads();

    const float* __restrict__ W = (half ? Wtp : Wt) + k;
    float acc[ROWS];
#pragma unroll
    for (int r = 0; r < ROWS; ++r) acc[r] = 0.f;

#pragma unroll 2
    for (int hh = 0; hh < HH; hh += 4) {
        // 4 W values, batched LDGs (stride HH -> no vector load possible)
        const float w0 = W[(hh + 0) * HH];
        const float w1 = W[(hh + 1) * HH];
        const float w2 = W[(hh + 2) * HH];
        const float w3 = W[(hh + 3) * HH];
        // 8 LDS.128 cover all rows for these 4 hh
        float4 hv[ROWS];
#pragma unroll
        for (int r = 0; r < ROWS; ++r)
            hv[r] = *reinterpret_cast<const float4*>(&sh[r][hh]);
#pragma unroll
        for (int r = 0; r < ROWS; ++r) {
            acc[r] = fmaf(hv[r].x, w0, acc[r]);
            acc[r] = fmaf(hv[r].y, w1, acc[r]);
            acc[r] = fmaf(hv[r].z, w2, acc[r]);
            acc[r] = fmaf(hv[r].w, w3, acc[r]);
        }
    }

    if (half == 0) {
        const float bias = bh[k];
#pragma unroll
        for (int r = 0; r < ROWS; ++r)
            g_ht_h[(row0 + r) * HH + k] = __float2half(acc[r] + bias);
    } else {
        __half* htpT = reinterpret_cast<__half*>(g_htpT);
#pragma unroll
        for (int r = 0; r < ROWS; ++r) {
            const int row = row0 + r;
            const int b   = row >> 9;
            const int tp  = row & (SS - 1);
            htpT[(((size_t)b * H4 + (k >> 2)) * SS + tp) * 4 + (k & 3)] = __float2half(acc[r]);
        }
    }
}

// ---------------------------------------------------------------------------
// Stage 2: pure (t, tp) score map, no normalization. (unchanged)
//   p[bt][tp] = exp(sigmoid(Wa . tanh(ht[t] + htp[tp]) + ba))
// ---------------------------------------------------------------------------
__global__ void __launch_bounds__(256)
score_kernel(const float* __restrict__ Wa,
             const float* __restrict__ ba)
{
    const int bt0 = blockIdx.y * 16;        // 16 rows, same batch (16 | 512)
    const int b   = bt0 >> 9;
    const int tid = threadIdx.x;
    const int w   = tid >> 5;
    const int lane= tid & 31;

    __shared__ uint4 su[16][H4];            // {ht01, ht23, wa01, wa23}  16KB

    for (int e = tid; e < 16 * H4; e += 256) {
        const int t  = e >> 6;
        const int h4 = e & 63;
        const uint2 ht4 = reinterpret_cast<const uint2*>(g_ht_h)[(bt0 + t) * (HH / 4) + h4];
        const float4 wa4 = reinterpret_cast<const float4*>(Wa)[h4];
        su[t][h4] = make_uint4(ht4.x, ht4.y,
                               h2u(__floats2half2_rn(wa4.x, wa4.y)),
                               h2u(__floats2half2_rn(wa4.z, wa4.w)));
    }
    __syncthreads();

    const float bav = ba[0];
    const int   tp  = blockIdx.x * 32 + lane;
    const int   r0  = 2 * w, r1 = 2 * w + 1;
    const uint2* hp = g_htpT + (size_t)b * H4 * SS + tp;

    float fa0 = 0.f, fa1 = 0.f;
    __half2 z = __floats2half2_rn(0.f, 0.f);
    __half2 acc0 = z, acc1 = z;

#pragma unroll 1
    for (int hb = 0; hb < 16; ++hb) {       // fold to fp32 every 4 h4
#pragma unroll
        for (int j = 0; j < 4; ++j) {
            const int h4 = hb * 4 + j;
            const uint2 x  = hp[(size_t)h4 * SS];
            const __half2 xa = u2h(x.x), xb = u2h(x.y);
            const uint4 u0 = su[r0][h4];
            const uint4 u1 = su[r1][h4];
            acc0 = __hfma2(u2h(u0.z), u2h(tanh2u(h2u(__hadd2(u2h(u0.x), xa)))), acc0);
            acc0 = __hfma2(u2h(u0.w), u2h(tanh2u(h2u(__hadd2(u2h(u0.y), xb)))), acc0);
            acc1 = __hfma2(u2h(u1.z), u2h(tanh2u(h2u(__hadd2(u2h(u1.x), xa)))), acc1);
            acc1 = __hfma2(u2h(u1.w), u2h(tanh2u(h2u(__hadd2(u2h(u1.y), xb)))), acc1);
        }
        const float2 f0 = __half22float2(acc0);
        const float2 f1 = __half22float2(acc1);
        fa0 += f0.x + f0.y;
        fa1 += f1.x + f1.y;
        acc0 = z; acc1 = z;
    }

    const float s0 = fa0 + bav;
    const float s1 = fa1 + bav;
    const float p0 = __expf(0.5f * tanh_fast(0.5f * s0) + 0.5f);
    const float p1 = __expf(0.5f * tanh_fast(0.5f * s1) + 0.5f);
    g_p[(size_t)(bt0 + r0) * SS + tp] = p0;
    g_p[(size_t)(bt0 + r1) * SS + tp] = p1;
}

// ---------------------------------------------------------------------------
// Stage 3: rowsum + normalize + output GEMM, 512 threads. (unchanged)
// ---------------------------------------------------------------------------
__global__ void __launch_bounds__(512)
out_kernel(const float* __restrict__ hin,
           float* __restrict__ out,
           float* __restrict__ wts)
{
    const int bt0 = blockIdx.x * 8;
    const int b   = bt0 >> 9;
    const int tid = threadIdx.x;
    const int w   = tid >> 5;
    const int lane= tid & 31;
    const int seg = tid >> 8;           // 0 or 1 (tp half)
    const int k   = tid & 255;

    __shared__ float pT[SS][8];             // transposed p (unnormalized)  16KB
    __shared__ float part[8][HH];           // seg-1 partial sums           8KB
    __shared__ float rinv[8];

    // Load p coalesced, store transposed.
    for (int e = tid; e < 8 * SS; e += 512) {
        const int t  = e >> 9;
        const int tp = e & (SS - 1);
        pT[tp][t] = g_p[(size_t)(bt0 + t) * SS + tp];
    }
    __syncthreads();

    // Rowsum: warps 0..7 own rows 0..7.
    if (w < 8) {
        float s = 0.f;
        for (int tp = lane; tp < SS; tp += 32) s += pT[tp][w];
#pragma unroll
        for (int off = 16; off > 0; off >>= 1)
            s += __shfl_xor_sync(0xffffffffu, s, off);
        if (lane == 0) rinv[w] = 1.0f / s;
    }
    __syncthreads();

    // Normalized weights output.
    if (wts) {
        for (int e = tid; e < 8 * SS; e += 512) {
            const int t  = e >> 9;
            const int tp = e & (SS - 1);
            wts[(size_t)(bt0 + t) * SS + tp] = pT[tp][t] * rinv[t];
        }
    }

    // GEMM with unnormalized p over this segment's tp range.
    float facc[8];
#pragma unroll
    for (int r = 0; r < 8; ++r) facc[r] = 0.f;
    const float* hb = hin + (size_t)b * SS * HH + k;
    const int tp0 = seg * 256;
#pragma unroll 4
    for (int i = 0; i < 256; ++i) {
        const int tp = tp0 + i;
        const float hv = hb[(size_t)tp * HH];
        const float4 wA = *reinterpret_cast<const float4*>(&pT[tp][0]);
        const float4 wB = *reinterpret_cast<const float4*>(&pT[tp][4]);
        facc[0] = fmaf(wA.x, hv, facc[0]);
        facc[1] = fmaf(wA.y, hv, facc[1]);
        facc[2] = fmaf(wA.z, hv, facc[2]);
        facc[3] = fmaf(wA.w, hv, facc[3]);
        facc[4] = fmaf(wB.x, hv, facc[4]);
        facc[5] = fmaf(wB.y, hv, facc[5]);
        facc[6] = fmaf(wB.z, hv, facc[6]);
        facc[7] = fmaf(wB.w, hv, facc[7]);
    }

    if (seg == 1) {
#pragma unroll
        for (int r = 0; r < 8; ++r) part[r][k] = facc[r];
    }
    __syncthreads();
    if (seg == 0) {
#pragma unroll
        for (int r = 0; r < 8; ++r)
            out[(size_t)(bt0 + r) * HH + k] = (facc[r] + part[r][k]) * rinv[r];
    }
}

// ---------------------------------------------------------------------------
extern "C" void kernel_launch(void* const* d_in, const int* in_sizes, int n_in,
                              void* d_out, int out_size)
{
    const float* h   = (const float*)d_in[0];
    const float* Wt  = (const float*)d_in[1];
    const float* Wtp = (const float*)d_in[2];
    const float* bh  = (const float*)d_in[3];
    const float* Wa  = (const float*)d_in[4];
    const float* ba  = (const float*)d_in[5];

    float* out = (float*)d_out;
    float* wts = nullptr;
    const int nOut = BB * SS * HH;   // 524288
    const int nW   = BB * SS * SS;   // 1048576
    if (out_size >= nOut + nW) wts = out + nOut;

    proj_kernel<<<BB * SS / 8, 512>>>(h, Wt, Wtp, bh);
    score_kernel<<<dim3(SS / 32, BB * SS / 16), 256>>>(Wa, ba);
    out_kernel<<<BB * SS / 8, 512>>>(h, out, wts);
}